// round 16
// baseline (speedup 1.0000x reference)
#include <cuda_runtime.h>
#include <cuda_bf16.h>

// ---------------- problem constants ----------------
constexpr int Bq  = 128;
constexpr int Tq  = 512;
constexpr int Aq  = 77;
constexpr int Hq  = 512;
constexpr int KWq = 10;
constexpr int KMq = 20;
constexpr int Uq  = 64;
constexpr int OUTq = 121;           // 6*KM + 1
constexpr int NCTA = 128;
constexpr int NTHR = 256;           // 8 warps (R14 best config)

// Padded K layout: [x:4 | w:80 | h1:512 | h2:512 | pad]
// lstm1: K=596 -> 10 chunks (640).  lstm2: K=1108 -> 18 chunks (1152).

// ---------------- persistent device state (transposed [feat][batch]) ----------------
__device__ float g_h1[2][Hq * Bq];
__device__ float g_h2[2][Hq * Bq];
__device__ float g_c1[Hq * Bq];
__device__ float g_c2[Hq * Bq];
__device__ float g_wp[80 * Bq];         // attention window, padded to 80 rows
__device__ float g_xT[Tq][4 * Bq];      // x transposed+padded: [t][k(4)][b]
__device__ float g_zero[Bq];            // zero row for padding chunks
__device__ float g_kappa[Bq * KWq];     // [b][k]
__device__ float g_h2all[Tq][Hq * Bq];  // all h2 states for deferred fc2
__device__ float g_raw[Tq][128 * Bq];   // raw fc2 outputs [t][o][b]
__device__ unsigned g_bar_cnt;
__device__ unsigned g_bar_gen;

// ---------------- helpers ----------------
__device__ __forceinline__ unsigned long long pk2(float v) {
    unsigned long long r; unsigned u = __float_as_uint(v);
    asm("mov.b64 %0, {%1, %1};" : "=l"(r) : "r"(u));
    return r;
}
__device__ __forceinline__ void fma2(unsigned long long& d, unsigned long long a, unsigned long long b) {
    asm("fma.rn.f32x2 %0, %1, %2, %0;" : "+l"(d) : "l"(a), "l"(b));
}
__device__ __forceinline__ float2 up2(unsigned long long v) {
    unsigned lo, hi;
    asm("mov.b64 {%0, %1}, %2;" : "=r"(lo), "=r"(hi) : "l"(v));
    float2 f; f.x = __uint_as_float(lo); f.y = __uint_as_float(hi); return f;
}
__device__ __forceinline__ float sigf(float x) { return 1.f / (1.f + expf(-x)); }

__device__ __forceinline__ unsigned prmt(unsigned a, unsigned b, unsigned s) {
    unsigned d; asm("prmt.b32 %0, %1, %2, %3;" : "=r"(d) : "r"(a), "r"(b), "r"(s));
    return d;
}
// pack fp32 -> (bf16 hi) | (bf16 lo residual)<<16, stored as float bits
__device__ __forceinline__ float pack_hl(float wv) {
    unsigned hs = (unsigned)__bfloat16_as_ushort(__float2bfloat16(wv));
    float hf = __uint_as_float(hs << 16);
    unsigned ls = (unsigned)__bfloat16_as_ushort(__float2bfloat16(wv - hf));
    return __uint_as_float(hs | (ls << 16));
}
__device__ __forceinline__ void mma_bf16(float* c,
    unsigned a0, unsigned a1, unsigned a2, unsigned a3,
    unsigned b0, unsigned b1)
{
    asm volatile(
        "mma.sync.aligned.m16n8k16.row.col.f32.bf16.bf16.f32 "
        "{%0,%1,%2,%3}, {%4,%5,%6,%7}, {%8,%9}, {%0,%1,%2,%3};"
        : "+f"(c[0]), "+f"(c[1]), "+f"(c[2]), "+f"(c[3])
        : "r"(a0), "r"(a1), "r"(a2), "r"(a3), "r"(b0), "r"(b1));
}

// Grid-wide barrier (cooperative-groups style).
__device__ __forceinline__ void grid_barrier() {
    __syncthreads();
    if (threadIdx.x == 0) {
        asm volatile("fence.acq_rel.gpu;" ::: "memory");
        unsigned gen = g_bar_gen;
        if (atomicAdd(&g_bar_cnt, 1u) == (unsigned)NCTA - 1u) {
            g_bar_cnt = 0u;
            asm volatile("fence.acq_rel.gpu;" ::: "memory");
            atomicExch(&g_bar_gen, gen + 1u);
        } else {
            unsigned cur;
            do {
                asm volatile("ld.acquire.gpu.u32 %0, [%1];"
                             : "=r"(cur) : "l"(&g_bar_gen));
            } while (cur == gen);
        }
        asm volatile("fence.acq_rel.gpu;" ::: "memory");
    }
    __syncthreads();
}

// ---------------- init: zero state + transpose x ----------------
__global__ void k_init(const float* __restrict__ x) {
    int i = blockIdx.x * 256 + threadIdx.x;
    if (i < Tq * 4 * Bq) {
        int t = i >> 9, r = i & 511, k = r >> 7, b = r & 127;
        g_xT[t][r] = (k < 3) ? x[(b * Tq + t) * 3 + k] : 0.f;
    }
    if (i < Hq * Bq) { g_h1[0][i] = 0.f; g_h2[0][i] = 0.f; g_c1[i] = 0.f; g_c2[i] = 0.f; }
    if (i < 80 * Bq)  g_wp[i] = 0.f;
    if (i < Bq)       g_zero[i] = 0.f;
    if (i < Bq * KWq) g_kappa[i] = 0.f;
    if (i == 0) { g_bar_cnt = 0u; g_bar_gen = 0u; }
}

// ---------------- async chunk stager: 8 warps, warp w copies rows {w, w+8, ...} ----------------
// 16B-unit XOR swizzle: element (k, b) lives at unit (b>>2) ^ (2*((k>>1)&3)).
__device__ __forceinline__ void stage_chunk(
    float* __restrict__ vbuf, int kk0, const float* __restrict__ xt,
    const float* __restrict__ hA, const float* __restrict__ hB, int tid)
{
    const int lane = tid & 31, w = tid >> 5;
    const int swz = 2 * ((w >> 1) & 3);   // (k>>1)&3 == (w>>1)&3 for rows {w, w+8, ...}
    #pragma unroll
    for (int it = 0; it < 8; ++it) {
        int k = it * 8 + w;
        int kk = kk0 + k;
        const float* src;                 // warp-uniform branch
        if (kk < 4)                           src = xt + kk * Bq;
        else if (kk < 84)                     src = g_wp + (kk - 4) * Bq;
        else if (kk < 596)                    src = hA + (kk - 84) * Bq;
        else if (hB != nullptr && kk < 1108)  src = hB + (kk - 596) * Bq;
        else                                  src = g_zero;
        unsigned daddr = (unsigned)__cvta_generic_to_shared(
            vbuf + k * 128 + ((lane ^ swz) << 2));
        asm volatile("cp.async.cg.shared.global [%0], [%1], 16;"
                     :: "r"(daddr), "l"(src + lane * 4) : "memory");
    }
    asm volatile("cp.async.commit_group;" ::: "memory");
}

// ---------------- one LSTM phase: 3x-BF16 (hi/lo split) mma GEMM + cell update ----------------
// Warp wp: ws = wp&3 owns k-slice [ws*16, ws*16+16) of each 64-K chunk;
// hb = wp>>2 owns batch half [hb*64, hb*64+64). acc = M16 x N64 per warp.
// Chunk processing order rotated by `shift` (w-dependent chunks 0,1 last in
// lstm2). `prestaged`: first two chunks' cp.async groups were already issued
// (hidden under the attention phase).
__device__ __forceinline__ void lstm_phase(
    int unit0, int tid,
    const float* __restrict__ xt,
    const float* __restrict__ w_s,        // packed bf16 hi/lo weights [k][16] (as float bits)
    const float* __restrict__ bias_s,
    const float* __restrict__ hA,
    const float* __restrict__ hB,
    float* __restrict__ h_out,
    float* __restrict__ c_st,
    float* __restrict__ h2all,
    int nch, int shift, int prestaged,
    float* __restrict__ vbase)            // 3 contiguous 8192-float buffers; z unions front
{
    const int lane = tid & 31, wp = tid >> 5;
    const int g = lane >> 2, q = lane & 3;
    const int ws = wp & 3, hb = wp >> 2;
    const int u0 = (hb << 4) + (g >> 2);
    const int q2 = 2 * q, g3 = g & 3;
    const unsigned* wk = (const unsigned*)w_s;

    float acc[8][4];
    #pragma unroll
    for (int i = 0; i < 8; ++i) { acc[i][0]=0.f; acc[i][1]=0.f; acc[i][2]=0.f; acc[i][3]=0.f; }

    if (!prestaged) {
        stage_chunk(vbase,        ((0 + shift) % nch) * 64, xt, hA, hB, tid);
        stage_chunk(vbase + 8192, ((1 + shift) % nch) * 64, xt, hA, hB, tid);
    }

    for (int c = 0; c < nch; ++c) {
        if (c + 1 < nch) {
            asm volatile("cp.async.wait_group 1;" ::: "memory");
        } else {
            asm volatile("cp.async.wait_group 0;" ::: "memory");
        }
        __syncthreads();                  // chunk c visible to all warps; WAR guard
        if (c + 2 < nch)
            stage_chunk(vbase + ((c + 2) % 3) * 8192,
                        ((c + 2 + shift) % nch) * 64, xt, hA, hB, tid);

        const float* cur = vbase + (c % 3) * 8192;

        const int oc = (c + shift) % nch;
        // ---- A fragments from packed hi/lo weights ----
        int base = (oc * 64 + ws * 16 + q2) * 16 + g;
        unsigned X0 = wk[base],       Y0 = wk[base + 16];
        unsigned X1 = wk[base + 8],   Y1 = wk[base + 24];
        unsigned X2 = wk[base + 128], Y2 = wk[base + 144];
        unsigned X3 = wk[base + 136], Y3 = wk[base + 152];
        unsigned a0h = prmt(X0, Y0, 0x5410), a0l = prmt(X0, Y0, 0x7632);
        unsigned a1h = prmt(X1, Y1, 0x5410), a1l = prmt(X1, Y1, 0x7632);
        unsigned a2h = prmt(X2, Y2, 0x5410), a2l = prmt(X2, Y2, 0x7632);
        unsigned a3h = prmt(X3, Y3, 0x5410), a3l = prmt(X3, Y3, 0x7632);

        const float* pr = cur + (ws * 16 + q2) * 128;
        #pragma unroll
        for (int nt = 0; nt < 8; ++nt) {
            int off = ((((u0 + 2 * nt)) ^ q2) << 2) + g3;
            float f00 = pr[off];
            float f01 = pr[off + 128];
            float f10 = pr[off + 1024];
            float f11 = pr[off + 1152];
            unsigned b0h, b0l, b1h, b1l;
            asm("cvt.rn.bf16x2.f32 %0, %1, %2;" : "=r"(b0h) : "f"(f01), "f"(f00));
            asm("cvt.rn.bf16x2.f32 %0, %1, %2;" : "=r"(b1h) : "f"(f11), "f"(f10));
            float h00 = __uint_as_float(b0h << 16);
            float h01 = __uint_as_float(b0h & 0xffff0000u);
            float h10 = __uint_as_float(b1h << 16);
            float h11 = __uint_as_float(b1h & 0xffff0000u);
            asm("cvt.rn.bf16x2.f32 %0, %1, %2;" : "=r"(b0l) : "f"(f01 - h01), "f"(f00 - h00));
            asm("cvt.rn.bf16x2.f32 %0, %1, %2;" : "=r"(b1l) : "f"(f11 - h11), "f"(f10 - h10));
            mma_bf16(acc[nt], a0h, a1h, a2h, a3h, b0l, b1l);   // ah*bl
            mma_bf16(acc[nt], a0l, a1l, a2l, a3l, b0h, b1h);   // al*bh
            mma_bf16(acc[nt], a0h, a1h, a2h, a3h, b0h, b1h);   // ah*bh
        }
    }

    __syncthreads();                      // all mma reads of v done; v-space -> z
    // z region: [(hb*4+ws)*16 + r][col 0..63], row stride 68 (8704 floats in v0..v1)
    {
        float* z = vbase;
        int zr0 = ((hb * 4 + ws) * 16 + g) * 68;
        int zr1 = zr0 + 8 * 68;
        #pragma unroll
        for (int nt = 0; nt < 8; ++nt) {
            int col = 8 * nt + q2;
            *(float2*)(z + zr0 + col) = make_float2(acc[nt][0], acc[nt][1]);
            *(float2*)(z + zr1 + col) = make_float2(acc[nt][2], acc[nt][3]);
        }
    }
    __syncthreads();

    // ---- cell: 256 threads x 2 = 4 units x 128 batch; sum 4 k-slice partials ----
    #pragma unroll
    for (int it = 0; it < 2; ++it) {
        int idx = tid + it * 256;
        int au = idx >> 7;
        int b  = idx & 127;
        int bh2 = b >> 6, b64 = b & 63;
        const float* z = vbase;
        float zg[4];
        #pragma unroll
        for (int gi = 0; gi < 4; ++gi) {
            int r = gi * 4 + au;
            float s = 0.f;
            #pragma unroll
            for (int w4 = 0; w4 < 4; ++w4)
                s += z[((bh2 * 4 + w4) * 16 + r) * 68 + b64];
            zg[gi] = s + bias_s[r];
        }
        int j = unit0 + au;
        float cold = c_st[j * Bq + b];
        float cn = sigf(zg[1]) * cold + sigf(zg[0]) * tanhf(zg[2]);
        float hn = sigf(zg[3]) * tanhf(cn);
        c_st[j * Bq + b] = cn;
        h_out[j * Bq + b] = hn;
        if (h2all) h2all[j * Bq + b] = hn;
    }
}

// ---------------- attention phase: CTA handles batch b = blockIdx.x ----------------
__device__ __forceinline__ void attn_phase(
    int b, int tid,
    const float* __restrict__ W_abk, const float* __restrict__ b_abk,
    const float* __restrict__ c_seq, const float* __restrict__ h1,
    float* __restrict__ s)
{
    float* h_s   = s;           // 512
    float* abk_s = s + 512;     // 32
    float* al    = s + 544;     // 10
    float* be    = s + 556;     // 10
    float* ka    = s + 568;     // 10
    float* phi   = s + 584;     // 64

    #pragma unroll
    for (int k = tid; k < Hq; k += NTHR) h_s[k] = h1[k * Bq + b];
    __syncthreads();

    int lane = tid & 31, wrp = tid >> 5;
    for (int r = wrp; r < 3 * KWq; r += 8) {
        float sm = 0.f;
        const float* wr = W_abk + r * Hq;
        #pragma unroll 4
        for (int k = lane; k < Hq; k += 32) sm += h_s[k] * wr[k];
        #pragma unroll
        for (int o = 16; o; o >>= 1) sm += __shfl_xor_sync(0xffffffffu, sm, o);
        if (lane == 0) abk_s[r] = sm + b_abk[r];
    }
    __syncthreads();
    if (tid < KWq) {
        float kap = g_kappa[b * KWq + tid] + expf(abk_s[2 * KWq + tid]);
        g_kappa[b * KWq + tid] = kap;
        al[tid] = expf(abk_s[tid]);
        be[tid] = expf(abk_s[KWq + tid]);
        ka[tid] = kap;
    }
    __syncthreads();
    if (tid < Uq) {
        float u = (float)tid;
        float sm = 0.f;
        #pragma unroll
        for (int k = 0; k < KWq; ++k) {
            float d = ka[k] - u;
            sm += al[k] * expf(-be[k] * d * d);
        }
        phi[tid] = sm;
    }
    __syncthreads();
    if (tid < Aq) {
        float sm = 0.f;
        #pragma unroll 8
        for (int u = 0; u < Uq; ++u) sm += phi[u] * c_seq[(b * Uq + u) * Aq + tid];
        g_wp[tid * Bq + b] = sm;
    }
}

// ---------------- persistent main kernel ----------------
// smem (floats): w1[640*16] | w2[1152*16] | v[3*64*128] | bs1[16] | bs2[16]
constexpr int SM_W1 = 0;
constexpr int SM_W2 = SM_W1 + 640 * 16;       // 10240
constexpr int SM_V0 = SM_W2 + 1152 * 16;      // 28672  (3 buffers; z unions V0..V1)
constexpr int SM_V2 = SM_V0 + 2 * 8192;       // attn scratch lives here (buffer 2)
constexpr int SM_B1 = SM_V0 + 3 * 8192;       // 53248
constexpr int SM_B2 = SM_B1 + 16;
constexpr int SM_TOT_FLOATS = SM_B2 + 16;     // 53280
constexpr int SM_BYTES = SM_TOT_FLOATS * 4;   // 213120

__global__ void __launch_bounds__(NTHR, 1) k_main(
    const float* __restrict__ c_seq,
    const float* __restrict__ Wih1, const float* __restrict__ Whh1,
    const float* __restrict__ bih1, const float* __restrict__ bhh1,
    const float* __restrict__ Wih2, const float* __restrict__ Whh2,
    const float* __restrict__ bih2, const float* __restrict__ bhh2,
    const float* __restrict__ W_abk, const float* __restrict__ b_abk)
{
    extern __shared__ float smem[];
    float* w1_s  = smem + SM_W1;
    float* w2_s  = smem + SM_W2;
    float* vbase = smem + SM_V0;
    float* asrc  = smem + SM_V2;          // attn scratch (8192 floats, buffer 2)
    float* bs1   = smem + SM_B1;
    float* bs2   = smem + SM_B2;

    const int tid = threadIdx.x;
    const int unit0 = blockIdx.x * 4;
    const int myb = blockIdx.x;

    // ---- one-time weight preload into smem, bf16 hi/lo packed ----
    for (int idx = tid; idx < 640 * 16; idx += NTHR) {
        int i = idx & 15, kk = idx >> 4;
        int r = ((i >> 2) * Hq) + unit0 + (i & 3);
        float wv = 0.f;
        if (kk < 3)                     wv = Wih1[r * 80 + kk];
        else if (kk >= 4 && kk < 81)    wv = Wih1[r * 80 + 3 + (kk - 4)];
        else if (kk >= 84 && kk < 596)  wv = Whh1[r * Hq + (kk - 84)];
        w1_s[idx] = pack_hl(wv);
    }
    for (int idx = tid; idx < 1152 * 16; idx += NTHR) {
        int i = idx & 15, kk = idx >> 4;
        int r = ((i >> 2) * Hq) + unit0 + (i & 3);
        float wv = 0.f;
        if (kk < 3)                      wv = Wih2[r * 592 + kk];
        else if (kk >= 4 && kk < 81)     wv = Wih2[r * 592 + 3 + (kk - 4)];
        else if (kk >= 84 && kk < 596)   wv = Wih2[r * 592 + 80 + (kk - 84)];
        else if (kk >= 596 && kk < 1108) wv = Whh2[r * Hq + (kk - 596)];
        w2_s[idx] = pack_hl(wv);
    }
    if (tid < 16) {
        int r = ((tid >> 2) * Hq) + unit0 + (tid & 3);
        bs1[tid] = bih1[r] + bhh1[r];
        bs2[tid] = bih2[r] + bhh2[r];
    }
    __syncthreads();

    for (int t = 0; t < Tq; ++t) {
        const int src = t & 1, dst = src ^ 1;
        // LSTM1: [x | w_{t-1} | h1_src], natural chunk order
        lstm_phase(unit0, tid, g_xT[t], w1_s, bs1,
                   g_h1[src], nullptr,
                   g_h1[dst], g_c1, nullptr,
                   10, /*shift=*/0, /*prestaged=*/0, vbase);
        grid_barrier();
        // Pre-stage lstm2 chunks 2,3 (pure h1/h2 — ready now); their L2 round
        // trip completes under the attention phase. w-chunks 0,1 run LAST.
        stage_chunk(vbase,        2 * 64, g_xT[t], g_h1[dst], g_h2[src], tid);
        stage_chunk(vbase + 8192, 3 * 64, g_xT[t], g_h1[dst], g_h2[src], tid);
        attn_phase(myb, tid, W_abk, b_abk, c_seq, g_h1[dst], asrc);
        grid_barrier();
        // LSTM2: [x | w_t | h1_new | h2_src], rotated order {2..17,0,1}
        lstm_phase(unit0, tid, g_xT[t], w2_s, bs2,
                   g_h1[dst], g_h2[src],
                   g_h2[dst], g_c2, g_h2all[t],
                   18, /*shift=*/2, /*prestaged=*/1, vbase);
        __syncthreads();
        // Cross-CTA hazards covered by the two barriers above; c/kappa are
        // CTA-private; h2(t) visibility for lstm2(t+1) established at bar1(t+1).
    }
}

// ---------------- deferred fc2: grid (8 out-groups, 512 timesteps) ----------------
__global__ void __launch_bounds__(256) k_fc2(const float* __restrict__ Wf, const float* __restrict__ bf)
{
    __shared__ float v_s[64][Bq];
    __shared__ float w_s[64][16];
    const int tid = threadIdx.x;
    const int tx = tid & 15, ty = tid >> 4, b0 = ty * 8;
    const int t = blockIdx.y, og = blockIdx.x;
    const int o = og * 16 + tx;

    unsigned long long a0=0,a1=0,a2=0,a3=0;
    for (int c = 0; c < 8; ++c) {
        const int kk0 = c * 64;
        const float4* sp = (const float4*)(g_h2all[t] + kk0 * Bq);
        float4* dp = (float4*)(&v_s[0][0]);
        #pragma unroll
        for (int i = 0; i < 8; ++i) dp[tid + i * 256] = sp[tid + i * 256];
        {
            int i = tid & 15, kq = tid >> 4;
            int oo = og * 16 + i;
            float4 wv = make_float4(0.f, 0.f, 0.f, 0.f);
            if (oo < OUTq) wv = *(const float4*)(Wf + oo * Hq + kk0 + kq * 4);
            w_s[kq * 4 + 0][i] = wv.x; w_s[kq * 4 + 1][i] = wv.y;
            w_s[kq * 4 + 2][i] = wv.z; w_s[kq * 4 + 3][i] = wv.w;
        }
        __syncthreads();
        #pragma unroll
        for (int k = 0; k < 64; ++k) {
            unsigned long long wp = pk2(w_s[k][tx]);
            ulonglong2 p0 = *(const ulonglong2*)&v_s[k][b0];
            ulonglong2 p1 = *(const ulonglong2*)&v_s[k][b0 + 4];
            fma2(a0, p0.x, wp); fma2(a1, p0.y, wp);
            fma2(a2, p1.x, wp); fma2(a3, p1.y, wp);
        }
        __syncthreads();
    }
    if (o < OUTq) {
        float bias = bf[o];
        float* dstp = &g_raw[t][o * Bq + b0];
        float2 f;
        f = up2(a0); dstp[0] = f.x + bias; dstp[1] = f.y + bias;
        f = up2(a1); dstp[2] = f.x + bias; dstp[3] = f.y + bias;
        f = up2(a2); dstp[4] = f.x + bias; dstp[5] = f.y + bias;
        f = up2(a3); dstp[6] = f.x + bias; dstp[7] = f.y + bias;
    }
}

// ---------------- MDN post-processing -> d_out ----------------
__global__ void __launch_bounds__(256) k_post(float* __restrict__ out)
{
    int idx = blockIdx.x * 256 + threadIdx.x;
    if (idx >= Bq * Tq) return;
    int b = idx & (Bq - 1);
    int t = idx >> 7;
    const float* raw = g_raw[t];
    const size_t BT = (size_t)Bq * Tq;
    const size_t base = (size_t)b * Tq + t;

    float v[KMq];
    float m = -1e30f;
    #pragma unroll
    for (int k = 0; k < KMq; ++k) { v[k] = raw[k * Bq + b]; m = fmaxf(m, v[k]); }
    float s = 0.f;
    #pragma unroll
    for (int k = 0; k < KMq; ++k) { v[k] = expf(v[k] - m); s += v[k]; }
    float inv = 1.f / s;
    #pragma unroll
    for (int k = 0; k < KMq; ++k) out[base * KMq + k] = v[k] * inv;

    float* mu1 = out + BT * KMq;
    float* mu2 = out + 2 * BT * KMq;
    float* s1  = out + 3 * BT * KMq;
    float* s2  = out + 4 * BT * KMq;
    float* co  = out + 5 * BT * KMq;
    #pragma unroll
    for (int k = 0; k < KMq; ++k) {
        mu1[base * KMq + k] = raw[(KMq + k) * Bq + b];
        mu2[base * KMq + k] = raw[(2 * KMq + k) * Bq + b];
        s1[base * KMq + k]  = expf(raw[(3 * KMq + k) * Bq + b]);
        s2[base * KMq + k]  = expf(raw[(4 * KMq + k) * Bq + b]);
        co[base * KMq + k]  = tanhf(raw[(5 * KMq + k) * Bq + b]);
    }
    out[6 * BT * KMq + base] = sigf(raw[(6 * KMq) * Bq + b]);
}

// ---------------- launch ----------------
extern "C" void kernel_launch(void* const* d_in, const int* in_sizes, int n_in,
                              void* d_out, int out_size)
{
    (void)in_sizes; (void)n_in; (void)out_size;
    const float* x     = (const float*)d_in[0];
    const float* c_seq = (const float*)d_in[1];
    const float* Wih1  = (const float*)d_in[2];
    const float* Whh1  = (const float*)d_in[3];
    const float* bih1  = (const float*)d_in[4];
    const float* bhh1  = (const float*)d_in[5];
    const float* Wih2  = (const float*)d_in[6];
    const float* Whh2  = (const float*)d_in[7];
    const float* bih2  = (const float*)d_in[8];
    const float* bhh2  = (const float*)d_in[9];
    const float* W_abk = (const float*)d_in[10];
    const float* b_abk = (const float*)d_in[11];
    const float* W_fc2 = (const float*)d_in[12];
    const float* b_fc2 = (const float*)d_in[13];

    static bool attr_done = false;
    if (!attr_done) {
        cudaFuncSetAttribute(k_main, cudaFuncAttributeMaxDynamicSharedMemorySize, SM_BYTES);
        attr_done = true;
    }

    k_init<<<1024, 256>>>(x);
    k_main<<<NCTA, NTHR, SM_BYTES>>>(c_seq, Wih1, Whh1, bih1, bhh1,
                                     Wih2, Whh2, bih2, bhh2, W_abk, b_abk);
    k_fc2<<<dim3(8, Tq), 256>>>(W_fc2, b_fc2);
    k_post<<<256, 256>>>((float*)d_out);
}

// round 17
// speedup vs baseline: 1.6401x; 1.6401x over previous
#include <cuda_runtime.h>
#include <cuda_bf16.h>

// ---------------- problem constants ----------------
constexpr int Bq  = 128;
constexpr int Tq  = 512;
constexpr int Aq  = 77;
constexpr int Hq  = 512;
constexpr int KWq = 10;
constexpr int KMq = 20;
constexpr int Uq  = 64;
constexpr int OUTq = 121;           // 6*KM + 1
constexpr int NCTA = 128;
constexpr int NTHR = 256;           // 8 warps (R14 best config)

// Padded K layout: [x:4 | w:80 | h1:512 | h2:512 | pad]
// lstm1: K=596 -> 10 chunks (640).  lstm2: K=1108 -> 18 chunks (1152).
// Activation storage format: one 32-bit word per element = (bf16_lo<<16)|bf16_hi
// (hi = bf16(v), lo = bf16(v - hi)). Consumers extract mma fragments with PRMT.

// ---------------- persistent device state (transposed [feat][batch]) ----------------
__device__ float g_h1[2][Hq * Bq];      // packed hi/lo words
__device__ float g_h2[2][Hq * Bq];      // packed hi/lo words
__device__ float g_c1[Hq * Bq];
__device__ float g_c2[Hq * Bq];
__device__ float g_wp[80 * Bq];         // packed hi/lo words, padded to 80 rows
__device__ float g_xT[Tq][4 * Bq];      // packed hi/lo words: [t][k(4)][b]
__device__ float g_zero[Bq];            // zero row (pack(0)=0)
__device__ float g_kappa[Bq * KWq];     // [b][k]
__device__ float g_h2all[Tq][Hq * Bq];  // fp32 h2 states for deferred fc2
__device__ float g_raw[Tq][128 * Bq];   // raw fc2 outputs [t][o][b]
__device__ unsigned g_bar_cnt;
__device__ unsigned g_bar_gen;

// ---------------- helpers ----------------
__device__ __forceinline__ unsigned long long pk2(float v) {
    unsigned long long r; unsigned u = __float_as_uint(v);
    asm("mov.b64 %0, {%1, %1};" : "=l"(r) : "r"(u));
    return r;
}
__device__ __forceinline__ void fma2(unsigned long long& d, unsigned long long a, unsigned long long b) {
    asm("fma.rn.f32x2 %0, %1, %2, %0;" : "+l"(d) : "l"(a), "l"(b));
}
__device__ __forceinline__ float2 up2(unsigned long long v) {
    unsigned lo, hi;
    asm("mov.b64 {%0, %1}, %2;" : "=r"(lo), "=r"(hi) : "l"(v));
    float2 f; f.x = __uint_as_float(lo); f.y = __uint_as_float(hi); return f;
}
__device__ __forceinline__ float sigf(float x) { return 1.f / (1.f + expf(-x)); }

__device__ __forceinline__ unsigned prmt(unsigned a, unsigned b, unsigned s) {
    unsigned d; asm("prmt.b32 %0, %1, %2, %3;" : "=r"(d) : "r"(a), "r"(b), "r"(s));
    return d;
}
// pack fp32 -> (bf16 lo residual)<<16 | (bf16 hi), stored as float bits
__device__ __forceinline__ float pack_hl(float wv) {
    unsigned hs = (unsigned)__bfloat16_as_ushort(__float2bfloat16(wv));
    float hf = __uint_as_float(hs << 16);
    unsigned ls = (unsigned)__bfloat16_as_ushort(__float2bfloat16(wv - hf));
    return __uint_as_float(hs | (ls << 16));
}
// unpack to ~fp32: hi + lo  (rel err ~2^-17)
__device__ __forceinline__ float unpack_hl(float pw) {
    unsigned w = __float_as_uint(pw);
    return __uint_as_float(w << 16) + __uint_as_float(w & 0xffff0000u);
}
__device__ __forceinline__ void mma_bf16(float* c,
    unsigned a0, unsigned a1, unsigned a2, unsigned a3,
    unsigned b0, unsigned b1)
{
    asm volatile(
        "mma.sync.aligned.m16n8k16.row.col.f32.bf16.bf16.f32 "
        "{%0,%1,%2,%3}, {%4,%5,%6,%7}, {%8,%9}, {%0,%1,%2,%3};"
        : "+f"(c[0]), "+f"(c[1]), "+f"(c[2]), "+f"(c[3])
        : "r"(a0), "r"(a1), "r"(a2), "r"(a3), "r"(b0), "r"(b1));
}

// Grid-wide barrier (cooperative-groups style).
__device__ __forceinline__ void grid_barrier() {
    __syncthreads();
    if (threadIdx.x == 0) {
        asm volatile("fence.acq_rel.gpu;" ::: "memory");
        unsigned gen = g_bar_gen;
        if (atomicAdd(&g_bar_cnt, 1u) == (unsigned)NCTA - 1u) {
            g_bar_cnt = 0u;
            asm volatile("fence.acq_rel.gpu;" ::: "memory");
            atomicExch(&g_bar_gen, gen + 1u);
        } else {
            unsigned cur;
            do {
                asm volatile("ld.acquire.gpu.u32 %0, [%1];"
                             : "=r"(cur) : "l"(&g_bar_gen));
            } while (cur == gen);
        }
        asm volatile("fence.acq_rel.gpu;" ::: "memory");
    }
    __syncthreads();
}

// ---------------- init: zero state + transpose+pack x ----------------
__global__ void k_init(const float* __restrict__ x) {
    int i = blockIdx.x * 256 + threadIdx.x;
    if (i < Tq * 4 * Bq) {
        int t = i >> 9, r = i & 511, k = r >> 7, b = r & 127;
        g_xT[t][r] = (k < 3) ? pack_hl(x[(b * Tq + t) * 3 + k]) : 0.f;
    }
    if (i < Hq * Bq) { g_h1[0][i] = 0.f; g_h2[0][i] = 0.f; g_c1[i] = 0.f; g_c2[i] = 0.f; }
    if (i < 80 * Bq)  g_wp[i] = 0.f;
    if (i < Bq)       g_zero[i] = 0.f;
    if (i < Bq * KWq) g_kappa[i] = 0.f;
    if (i == 0) { g_bar_cnt = 0u; g_bar_gen = 0u; }
}

// ---------------- async chunk stager: 8 warps, warp w copies rows {w, w+8, ...} ----------------
// 16B-unit XOR swizzle: element (k, b) lives at unit (b>>2) ^ (2*((k>>1)&3)).
__device__ __forceinline__ void stage_chunk(
    float* __restrict__ vbuf, int kk0, const float* __restrict__ xt,
    const float* __restrict__ hA, const float* __restrict__ hB, int tid)
{
    const int lane = tid & 31, w = tid >> 5;
    const int swz = 2 * ((w >> 1) & 3);   // (k>>1)&3 == (w>>1)&3 for rows {w, w+8, ...}
    #pragma unroll
    for (int it = 0; it < 8; ++it) {
        int k = it * 8 + w;
        int kk = kk0 + k;
        const float* src;                 // warp-uniform branch
        if (kk < 4)                           src = xt + kk * Bq;
        else if (kk < 84)                     src = g_wp + (kk - 4) * Bq;
        else if (kk < 596)                    src = hA + (kk - 84) * Bq;
        else if (hB != nullptr && kk < 1108)  src = hB + (kk - 596) * Bq;
        else                                  src = g_zero;
        unsigned daddr = (unsigned)__cvta_generic_to_shared(
            vbuf + k * 128 + ((lane ^ swz) << 2));
        asm volatile("cp.async.cg.shared.global [%0], [%1], 16;"
                     :: "r"(daddr), "l"(src + lane * 4) : "memory");
    }
    asm volatile("cp.async.commit_group;" ::: "memory");
}

// ---------------- one LSTM phase: 3x-BF16 (packed hi/lo) mma GEMM + cell update ----------------
// Warp wp: ws = wp&3 owns k-slice [ws*16, ws*16+16) of each 64-K chunk;
// hb = wp>>2 owns batch half [hb*64, hb*64+64). acc = M16 x N64 per warp.
// 3-term product: ah*bl + al*bh + ah*bh; B fragments via PRMT on packed words.
__device__ __forceinline__ void lstm_phase(
    int unit0, int tid,
    const float* __restrict__ xt,
    const float* __restrict__ w_s,        // packed bf16 hi/lo weights [k][16] (as float bits)
    const float* __restrict__ bias_s,
    const float* __restrict__ hA,
    const float* __restrict__ hB,
    float* __restrict__ h_out,            // packed hi/lo output
    float* __restrict__ c_st,
    float* __restrict__ h2all,            // fp32 output (fc2)
    int nch,
    float* __restrict__ vbase)            // 3 contiguous 8192-float buffers; z unions front
{
    const int lane = tid & 31, wp = tid >> 5;
    const int g = lane >> 2, q = lane & 3;
    const int ws = wp & 3, hb = wp >> 2;
    const int u0 = (hb << 4) + (g >> 2);
    const int q2 = 2 * q, g3 = g & 3;
    const unsigned* wk = (const unsigned*)w_s;

    float acc[8][4];
    #pragma unroll
    for (int i = 0; i < 8; ++i) { acc[i][0]=0.f; acc[i][1]=0.f; acc[i][2]=0.f; acc[i][3]=0.f; }

    stage_chunk(vbase,        0,  xt, hA, hB, tid);
    stage_chunk(vbase + 8192, 64, xt, hA, hB, tid);

    for (int c = 0; c < nch; ++c) {
        if (c + 1 < nch) {
            asm volatile("cp.async.wait_group 1;" ::: "memory");
        } else {
            asm volatile("cp.async.wait_group 0;" ::: "memory");
        }
        __syncthreads();                  // chunk c visible to all warps; WAR guard
        if (c + 2 < nch)
            stage_chunk(vbase + ((c + 2) % 3) * 8192, (c + 2) * 64, xt, hA, hB, tid);

        const float* cur = vbase + (c % 3) * 8192;

        // ---- A fragments from packed hi/lo weights ----
        int base = (c * 64 + ws * 16 + q2) * 16 + g;
        unsigned X0 = wk[base],       Y0 = wk[base + 16];
        unsigned X1 = wk[base + 8],   Y1 = wk[base + 24];
        unsigned X2 = wk[base + 128], Y2 = wk[base + 144];
        unsigned X3 = wk[base + 136], Y3 = wk[base + 152];
        unsigned a0h = prmt(X0, Y0, 0x5410), a0l = prmt(X0, Y0, 0x7632);
        unsigned a1h = prmt(X1, Y1, 0x5410), a1l = prmt(X1, Y1, 0x7632);
        unsigned a2h = prmt(X2, Y2, 0x5410), a2l = prmt(X2, Y2, 0x7632);
        unsigned a3h = prmt(X3, Y3, 0x5410), a3l = prmt(X3, Y3, 0x7632);

        // ---- B fragments from packed hi/lo activations (PRMT only) ----
        const unsigned* pr = (const unsigned*)cur + (ws * 16 + q2) * 128;
        #pragma unroll
        for (int nt = 0; nt < 8; ++nt) {
            int off = ((((u0 + 2 * nt)) ^ q2) << 2) + g3;
            unsigned w00 = pr[off];
            unsigned w01 = pr[off + 128];
            unsigned w10 = pr[off + 1024];
            unsigned w11 = pr[off + 1152];
            unsigned b0h = prmt(w00, w01, 0x5410), b0l = prmt(w00, w01, 0x7632);
            unsigned b1h = prmt(w10, w11, 0x5410), b1l = prmt(w10, w11, 0x7632);
            mma_bf16(acc[nt], a0h, a1h, a2h, a3h, b0l, b1l);   // ah*bl
            mma_bf16(acc[nt], a0l, a1l, a2l, a3l, b0h, b1h);   // al*bh
            mma_bf16(acc[nt], a0h, a1h, a2h, a3h, b0h, b1h);   // ah*bh
        }
    }

    __syncthreads();                      // all mma reads of v done; v-space -> z
    // z region: [(hb*4+ws)*16 + r][col 0..63], row stride 68 (8704 floats in v0..v1)
    {
        float* z = vbase;
        int zr0 = ((hb * 4 + ws) * 16 + g) * 68;
        int zr1 = zr0 + 8 * 68;
        #pragma unroll
        for (int nt = 0; nt < 8; ++nt) {
            int col = 8 * nt + q2;
            *(float2*)(z + zr0 + col) = make_float2(acc[nt][0], acc[nt][1]);
            *(float2*)(z + zr1 + col) = make_float2(acc[nt][2], acc[nt][3]);
        }
    }
    __syncthreads();

    // ---- cell: 256 threads x 2 = 4 units x 128 batch; sum 4 k-slice partials ----
    #pragma unroll
    for (int it = 0; it < 2; ++it) {
        int idx = tid + it * 256;
        int au = idx >> 7;
        int b  = idx & 127;
        int bh2 = b >> 6, b64 = b & 63;
        const float* z = vbase;
        float zg[4];
        #pragma unroll
        for (int gi = 0; gi < 4; ++gi) {
            int r = gi * 4 + au;
            float s = 0.f;
            #pragma unroll
            for (int w4 = 0; w4 < 4; ++w4)
                s += z[((bh2 * 4 + w4) * 16 + r) * 68 + b64];
            zg[gi] = s + bias_s[r];
        }
        int j = unit0 + au;
        float cold = c_st[j * Bq + b];
        float cn = sigf(zg[1]) * cold + sigf(zg[0]) * tanhf(zg[2]);
        float hn = sigf(zg[3]) * tanhf(cn);
        c_st[j * Bq + b] = cn;
        h_out[j * Bq + b] = pack_hl(hn);
        if (h2all) h2all[j * Bq + b] = hn;
    }
}

// ---------------- attention phase: CTA handles batch b = blockIdx.x ----------------
__device__ __forceinline__ void attn_phase(
    int b, int tid,
    const float* __restrict__ W_abk, const float* __restrict__ b_abk,
    const float* __restrict__ c_seq, const float* __restrict__ h1,
    float* __restrict__ s)
{
    float* h_s   = s;           // 512
    float* abk_s = s + 512;     // 32
    float* al    = s + 544;     // 10
    float* be    = s + 556;     // 10
    float* ka    = s + 568;     // 10
    float* phi   = s + 584;     // 64

    #pragma unroll
    for (int k = tid; k < Hq; k += NTHR) h_s[k] = unpack_hl(h1[k * Bq + b]);
    __syncthreads();

    int lane = tid & 31, wrp = tid >> 5;
    for (int r = wrp; r < 3 * KWq; r += 8) {
        float sm = 0.f;
        const float* wr = W_abk + r * Hq;
        #pragma unroll 4
        for (int k = lane; k < Hq; k += 32) sm += h_s[k] * wr[k];
        #pragma unroll
        for (int o = 16; o; o >>= 1) sm += __shfl_xor_sync(0xffffffffu, sm, o);
        if (lane == 0) abk_s[r] = sm + b_abk[r];
    }
    __syncthreads();
    if (tid < KWq) {
        float kap = g_kappa[b * KWq + tid] + expf(abk_s[2 * KWq + tid]);
        g_kappa[b * KWq + tid] = kap;
        al[tid] = expf(abk_s[tid]);
        be[tid] = expf(abk_s[KWq + tid]);
        ka[tid] = kap;
    }
    __syncthreads();
    if (tid < Uq) {
        float u = (float)tid;
        float sm = 0.f;
        #pragma unroll
        for (int k = 0; k < KWq; ++k) {
            float d = ka[k] - u;
            sm += al[k] * expf(-be[k] * d * d);
        }
        phi[tid] = sm;
    }
    __syncthreads();
    if (tid < Aq) {
        float sm = 0.f;
        #pragma unroll 8
        for (int u = 0; u < Uq; ++u) sm += phi[u] * c_seq[(b * Uq + u) * Aq + tid];
        g_wp[tid * Bq + b] = pack_hl(sm);
    }
}

// ---------------- persistent main kernel ----------------
// smem (floats): w1[640*16] | w2[1152*16] | v[3*64*128] | bs1[16] | bs2[16]
constexpr int SM_W1 = 0;
constexpr int SM_W2 = SM_W1 + 640 * 16;       // 10240
constexpr int SM_V0 = SM_W2 + 1152 * 16;      // 28672  (3 buffers; z unions V0..V1)
constexpr int SM_V2 = SM_V0 + 2 * 8192;       // attn scratch lives here (buffer 2)
constexpr int SM_B1 = SM_V0 + 3 * 8192;       // 53248
constexpr int SM_B2 = SM_B1 + 16;
constexpr int SM_TOT_FLOATS = SM_B2 + 16;     // 53280
constexpr int SM_BYTES = SM_TOT_FLOATS * 4;   // 213120

__global__ void __launch_bounds__(NTHR, 1) k_main(
    const float* __restrict__ c_seq,
    const float* __restrict__ Wih1, const float* __restrict__ Whh1,
    const float* __restrict__ bih1, const float* __restrict__ bhh1,
    const float* __restrict__ Wih2, const float* __restrict__ Whh2,
    const float* __restrict__ bih2, const float* __restrict__ bhh2,
    const float* __restrict__ W_abk, const float* __restrict__ b_abk)
{
    extern __shared__ float smem[];
    float* w1_s  = smem + SM_W1;
    float* w2_s  = smem + SM_W2;
    float* vbase = smem + SM_V0;
    float* asrc  = smem + SM_V2;          // attn scratch (8192 floats, buffer 2)
    float* bs1   = smem + SM_B1;
    float* bs2   = smem + SM_B2;

    const int tid = threadIdx.x;
    const int unit0 = blockIdx.x * 4;
    const int myb = blockIdx.x;

    // ---- one-time weight preload into smem, bf16 hi/lo packed ----
    for (int idx = tid; idx < 640 * 16; idx += NTHR) {
        int i = idx & 15, kk = idx >> 4;
        int r = ((i >> 2) * Hq) + unit0 + (i & 3);
        float wv = 0.f;
        if (kk < 3)                     wv = Wih1[r * 80 + kk];
        else if (kk >= 4 && kk < 81)    wv = Wih1[r * 80 + 3 + (kk - 4)];
        else if (kk >= 84 && kk < 596)  wv = Whh1[r * Hq + (kk - 84)];
        w1_s[idx] = pack_hl(wv);
    }
    for (int idx = tid; idx < 1152 * 16; idx += NTHR) {
        int i = idx & 15, kk = idx >> 4;
        int r = ((i >> 2) * Hq) + unit0 + (i & 3);
        float wv = 0.f;
        if (kk < 3)                      wv = Wih2[r * 592 + kk];
        else if (kk >= 4 && kk < 81)     wv = Wih2[r * 592 + 3 + (kk - 4)];
        else if (kk >= 84 && kk < 596)   wv = Wih2[r * 592 + 80 + (kk - 84)];
        else if (kk >= 596 && kk < 1108) wv = Whh2[r * Hq + (kk - 596)];
        w2_s[idx] = pack_hl(wv);
    }
    if (tid < 16) {
        int r = ((tid >> 2) * Hq) + unit0 + (tid & 3);
        bs1[tid] = bih1[r] + bhh1[r];
        bs2[tid] = bih2[r] + bhh2[r];
    }
    __syncthreads();

    for (int t = 0; t < Tq; ++t) {
        const int src = t & 1, dst = src ^ 1;
        // LSTM1: [x | w_{t-1} | h1_src]
        lstm_phase(unit0, tid, g_xT[t], w1_s, bs1,
                   g_h1[src], nullptr,
                   g_h1[dst], g_c1, nullptr,
                   10, vbase);
        grid_barrier();
        attn_phase(myb, tid, W_abk, b_abk, c_seq, g_h1[dst], asrc);
        grid_barrier();
        // LSTM2: [x | w_t | h1_new | h2_src]
        lstm_phase(unit0, tid, g_xT[t], w2_s, bs2,
                   g_h1[dst], g_h2[src],
                   g_h2[dst], g_c2, g_h2all[t],
                   18, vbase);
        __syncthreads();
        // Cross-CTA hazards covered by the two barriers above; c/kappa are
        // CTA-private; h2(t) visibility for lstm2(t+1) established at bar1(t+1).
    }
}

// ---------------- deferred fc2: grid (8 out-groups, 512 timesteps) ----------------
__global__ void __launch_bounds__(256) k_fc2(const float* __restrict__ Wf, const float* __restrict__ bf)
{
    __shared__ float v_s[64][Bq];
    __shared__ float w_s[64][16];
    const int tid = threadIdx.x;
    const int tx = tid & 15, ty = tid >> 4, b0 = ty * 8;
    const int t = blockIdx.y, og = blockIdx.x;
    const int o = og * 16 + tx;

    unsigned long long a0=0,a1=0,a2=0,a3=0;
    for (int c = 0; c < 8; ++c) {
        const int kk0 = c * 64;
        const float4* sp = (const float4*)(g_h2all[t] + kk0 * Bq);
        float4* dp = (float4*)(&v_s[0][0]);
        #pragma unroll
        for (int i = 0; i < 8; ++i) dp[tid + i * 256] = sp[tid + i * 256];
        {
            int i = tid & 15, kq = tid >> 4;
            int oo = og * 16 + i;
            float4 wv = make_float4(0.f, 0.f, 0.f, 0.f);
            if (oo < OUTq) wv = *(const float4*)(Wf + oo * Hq + kk0 + kq * 4);
            w_s[kq * 4 + 0][i] = wv.x; w_s[kq * 4 + 1][i] = wv.y;
            w_s[kq * 4 + 2][i] = wv.z; w_s[kq * 4 + 3][i] = wv.w;
        }
        __syncthreads();
        #pragma unroll
        for (int k = 0; k < 64; ++k) {
            unsigned long long wp = pk2(w_s[k][tx]);
            ulonglong2 p0 = *(const ulonglong2*)&v_s[k][b0];
            ulonglong2 p1 = *(const ulonglong2*)&v_s[k][b0 + 4];
            fma2(a0, p0.x, wp); fma2(a1, p0.y, wp);
            fma2(a2, p1.x, wp); fma2(a3, p1.y, wp);
        }
        __syncthreads();
    }
    if (o < OUTq) {
        float bias = bf[o];
        float* dstp = &g_raw[t][o * Bq + b0];
        float2 f;
        f = up2(a0); dstp[0] = f.x + bias; dstp[1] = f.y + bias;
        f = up2(a1); dstp[2] = f.x + bias; dstp[3] = f.y + bias;
        f = up2(a2); dstp[4] = f.x + bias; dstp[5] = f.y + bias;
        f = up2(a3); dstp[6] = f.x + bias; dstp[7] = f.y + bias;
    }
}

// ---------------- MDN post-processing -> d_out ----------------
__global__ void __launch_bounds__(256) k_post(float* __restrict__ out)
{
    int idx = blockIdx.x * 256 + threadIdx.x;
    if (idx >= Bq * Tq) return;
    int b = idx & (Bq - 1);
    int t = idx >> 7;
    const float* raw = g_raw[t];
    const size_t BT = (size_t)Bq * Tq;
    const size_t base = (size_t)b * Tq + t;

    float v[KMq];
    float m = -1e30f;
    #pragma unroll
    for (int k = 0; k < KMq; ++k) { v[k] = raw[k * Bq + b]; m = fmaxf(m, v[k]); }
    float s = 0.f;
    #pragma unroll
    for (int k = 0; k < KMq; ++k) { v[k] = expf(v[k] - m); s += v[k]; }
    float inv = 1.f / s;
    #pragma unroll
    for (int k = 0; k < KMq; ++k) out[base * KMq + k] = v[k] * inv;

    float* mu1 = out + BT * KMq;
    float* mu2 = out + 2 * BT * KMq;
    float* s1  = out + 3 * BT * KMq;
    float* s2  = out + 4 * BT * KMq;
    float* co  = out + 5 * BT * KMq;
    #pragma unroll
    for (int k = 0; k < KMq; ++k) {
        mu1[base * KMq + k] = raw[(KMq + k) * Bq + b];
        mu2[base * KMq + k] = raw[(2 * KMq + k) * Bq + b];
        s1[base * KMq + k]  = expf(raw[(3 * KMq + k) * Bq + b]);
        s2[base * KMq + k]  = expf(raw[(4 * KMq + k) * Bq + b]);
        co[base * KMq + k]  = tanhf(raw[(5 * KMq + k) * Bq + b]);
    }
    out[6 * BT * KMq + base] = sigf(raw[(6 * KMq) * Bq + b]);
}

// ---------------- launch ----------------
extern "C" void kernel_launch(void* const* d_in, const int* in_sizes, int n_in,
                              void* d_out, int out_size)
{
    (void)in_sizes; (void)n_in; (void)out_size;
    const float* x     = (const float*)d_in[0];
    const float* c_seq = (const float*)d_in[1];
    const float* Wih1  = (const float*)d_in[2];
    const float* Whh1  = (const float*)d_in[3];
    const float* bih1  = (const float*)d_in[4];
    const float* bhh1  = (const float*)d_in[5];
    const float* Wih2  = (const float*)d_in[6];
    const float* Whh2  = (const float*)d_in[7];
    const float* bih2  = (const float*)d_in[8];
    const float* bhh2  = (const float*)d_in[9];
    const float* W_abk = (const float*)d_in[10];
    const float* b_abk = (const float*)d_in[11];
    const float* W_fc2 = (const float*)d_in[12];
    const float* b_fc2 = (const float*)d_in[13];

    static bool attr_done = false;
    if (!attr_done) {
        cudaFuncSetAttribute(k_main, cudaFuncAttributeMaxDynamicSharedMemorySize, SM_BYTES);
        attr_done = true;
    }

    k_init<<<1024, 256>>>(x);
    k_main<<<NCTA, NTHR, SM_BYTES>>>(c_seq, Wih1, Whh1, bih1, bhh1,
                                     Wih2, Whh2, bih2, bhh2, W_abk, b_abk);
    k_fc2<<<dim3(8, Tq), 256>>>(W_fc2, b_fc2);
    k_post<<<256, 256>>>((float*)d_out);
}